// round 14
// baseline (speedup 1.0000x reference)
#include <cuda_runtime.h>
#include <cstdint>

#define BATCH 128
#define SEQ   512
#define DIM   768
#define MAXC  64
#define NT    256
#define NWARPS 8
#define ROW_BYTES (DIM * 4)                   // 3072
#define SMEM_ROWS_BYTES (MAXC * ROW_BYTES)    // 196608
#define SMEM_TOTAL (SMEM_ROWS_BYTES + NWARPS * 8)

__device__ __forceinline__ uint32_t smem_u32(const void* p) {
    uint32_t a;
    asm("{ .reg .u64 t; cvta.to.shared.u64 t, %1; cvt.u32.u64 %0, t; }" : "=r"(a) : "l"(p));
    return a;
}

__device__ __forceinline__ void mbar_init(uint32_t mbar, uint32_t count) {
    asm volatile("mbarrier.init.shared.b64 [%0], %1;" :: "r"(mbar), "r"(count) : "memory");
}
__device__ __forceinline__ void mbar_expect_tx(uint32_t mbar, uint32_t bytes) {
    asm volatile("mbarrier.arrive.expect_tx.shared.b64 _, [%0], %1;" :: "r"(mbar), "r"(bytes) : "memory");
}
__device__ __forceinline__ void bulk_copy_g2s(uint32_t dst_smem, const void* src, uint32_t bytes, uint32_t mbar) {
    asm volatile("cp.async.bulk.shared::cluster.global.mbarrier::complete_tx::bytes [%0], [%1], %2, [%3];"
                 :: "r"(dst_smem), "l"(src), "r"(bytes), "r"(mbar) : "memory");
}
__device__ __forceinline__ void mbar_wait(uint32_t mbar, uint32_t parity) {
    uint32_t done;
    asm volatile(
        "{\n\t.reg .pred p;\n\t"
        "mbarrier.try_wait.parity.acquire.cta.shared::cta.b64 p, [%1], %2;\n\t"
        "selp.b32 %0, 1, 0, p;\n\t}"
        : "=r"(done) : "r"(mbar), "r"(parity) : "memory");
    if (!done) {
        asm volatile(
            "{\n\t.reg .pred P1;\n\t"
            "W_%=:\n\t"
            "mbarrier.try_wait.parity.acquire.cta.shared::cta.b64 P1, [%0], %1, 0x989680;\n\t"
            "@P1 bra.uni D_%=;\n\t"
            "bra.uni W_%=;\n\t"
            "D_%=:\n\t}"
            :: "r"(mbar), "r"(parity) : "memory");
    }
}

__global__ __launch_bounds__(NT, 1)
void summarizer_kernel(const float* __restrict__ enc,
                       const float* __restrict__ W,
                       const float* __restrict__ bias,
                       const int* __restrict__ cls,
                       float* __restrict__ out) {
    extern __shared__ char dynsmem[];
    float* rowbuf = reinterpret_cast<float*>(dynsmem);
    const uint32_t rowbuf_u32 = smem_u32(dynsmem);
    const uint32_t mbar_base  = rowbuf_u32 + SMEM_ROWS_BYTES;

    __shared__ int sidx[MAXC];
    __shared__ int wtot[NWARPS];

    const int b    = blockIdx.x;
    const int tid  = threadIdx.x;
    const int lane = tid & 31;
    const int warp = tid >> 5;

    if (tid < NWARPS) mbar_init(mbar_base + tid * 8, 1);
    if (tid < MAXC) sidx[tid] = -1;

    // ---- Phase 1: compaction scan (2 positions / thread) ----
    const int2 cv = reinterpret_cast<const int2*>(cls + (size_t)b * SEQ)[tid];
    const int f0 = (cv.x != 0), f1 = (cv.y != 0);
    const int cnt = f0 + f1;

    int s = cnt;
    #pragma unroll
    for (int off = 1; off < 32; off <<= 1) {
        int n = __shfl_up_sync(0xffffffffu, s, off);
        if (lane >= off) s += n;
    }
    const int excl = s - cnt;
    if (lane == 31) wtot[warp] = s;
    __syncthreads();

    int base0 = 0;
    #pragma unroll
    for (int i = 0; i < NWARPS; i++) base0 += (i < warp) ? wtot[i] : 0;
    {
        int r = base0 + excl;
        const int p = tid * 2;
        if (f0) { if (r < MAXC) sidx[r] = p;     r++; }
        if (f1) { if (r < MAXC) sidx[r] = p + 1; }
    }
    __syncthreads();

    // ---- Phase 2: each warp owns 8 ranks; async-bulk its rows into smem ----
    const int rbase = warp * 8;
    int pv[8];
    #pragma unroll
    for (int i = 0; i < 8; i++) pv[i] = sidx[rbase + i];
    int nvalid = 0;
    #pragma unroll
    for (int i = 0; i < 8; i++) nvalid += (pv[i] >= 0);

    const float bv = bias[0];

    if (nvalid == 0) {
        if (lane == 0) {
            const float v = 1.0f / (1.0f + __expf(-bv));
            #pragma unroll
            for (int i = 0; i < 8; i++) out[b * MAXC + rbase + i] = v;
        }
        return;
    }

    const uint32_t mbar = mbar_base + warp * 8;
    if (lane == 0) {
        mbar_expect_tx(mbar, (uint32_t)nvalid * ROW_BYTES);
        for (int i = 0; i < nvalid; i++) {
            bulk_copy_g2s(rowbuf_u32 + (uint32_t)(rbase + i) * ROW_BYTES,
                          enc + ((size_t)b * SEQ + pv[i]) * DIM,
                          ROW_BYTES, mbar);
        }
    }
    __syncwarp();   // no lane reaches the wait before expect_tx is issued

    // W into registers while copies are in flight (L2-hot after first wave).
    const float4* __restrict__ w4 = reinterpret_cast<const float4*>(W);
    const float4 w0 = w4[lane +   0];
    const float4 w1 = w4[lane +  32];
    const float4 w2 = w4[lane +  64];
    const float4 w3 = w4[lane +  96];
    const float4 w4v = w4[lane + 128];
    const float4 w5 = w4[lane + 160];

    mbar_wait(mbar, 0);

    float acc[8];
    #pragma unroll
    for (int i = 0; i < 8; i++) acc[i] = 0.0f;

    #pragma unroll
    for (int i = 0; i < 8; i++) {
        if (i < nvalid) {
            const float4* rp = reinterpret_cast<const float4*>(rowbuf + (size_t)(rbase + i) * DIM);
            float4 a0 = rp[lane +   0];
            float4 a1 = rp[lane +  32];
            float4 a2 = rp[lane +  64];
            float4 a3 = rp[lane +  96];
            float4 a4 = rp[lane + 128];
            float4 a5 = rp[lane + 160];
            float t = 0.0f;
            t += a0.x*w0.x + a0.y*w0.y + a0.z*w0.z + a0.w*w0.w;
            t += a1.x*w1.x + a1.y*w1.y + a1.z*w1.z + a1.w*w1.w;
            t += a2.x*w2.x + a2.y*w2.y + a2.z*w2.z + a2.w*w2.w;
            t += a3.x*w3.x + a3.y*w3.y + a3.z*w3.z + a3.w*w3.w;
            t += a4.x*w4v.x + a4.y*w4v.y + a4.z*w4v.z + a4.w*w4v.w;
            t += a5.x*w5.x + a5.y*w5.y + a5.z*w5.z + a5.w*w5.w;
            acc[i] = t;
        }
    }

    // Interleaved warp reductions (8 independent chains).
    #pragma unroll
    for (int off = 16; off > 0; off >>= 1) {
        #pragma unroll
        for (int i = 0; i < 8; i++)
            acc[i] += __shfl_down_sync(0xffffffffu, acc[i], off);
    }

    if (lane == 0) {
        #pragma unroll
        for (int i = 0; i < 8; i++)
            out[b * MAXC + rbase + i] = 1.0f / (1.0f + __expf(-(acc[i] + bv)));
    }
}

extern "C" void kernel_launch(void* const* d_in, const int* in_sizes, int n_in,
                              void* d_out, int out_size) {
    const float* enc  = (const float*)d_in[0];
    const float* W    = (const float*)d_in[1];
    const float* bias = (const float*)d_in[2];
    const int*   cls  = (const int*)d_in[3];
    float* out = (float*)d_out;

    static bool attr_set = false;
    if (!attr_set) {
        cudaFuncSetAttribute(summarizer_kernel,
                             cudaFuncAttributeMaxDynamicSharedMemorySize, SMEM_TOTAL);
        attr_set = true;
    }
    summarizer_kernel<<<BATCH, NT, SMEM_TOTAL>>>(enc, W, bias, cls, out);
}